// round 2
// baseline (speedup 1.0000x reference)
#include <cuda_runtime.h>

#define NN 4096
#define MM 128
#define KK 32
#define GG 16
#define NS 8
#define CHUNK (NN / NS)   // 512

// Scratch (device globals: no allocation allowed)
__device__ float g_V[NN * KK];                 // transported-solve vectors v_i
__device__ float g_partZ[MM * NS];
__device__ float g_partCnt[MM * NS];
__device__ float g_partS1[MM * NS * KK];
__device__ float g_partS2[MM * NS * KK * KK];

// ---------------------------------------------------------------------------
// Kernel 1: per-i, solve (sum_g oc[i,g]) x = (sum_g mu[i,g])  -> v_i
// (The 1/G factors cancel between A and b.)
// One block per i, 128 threads. A stored in smem with row stride 33
// (col 32 holds b); stride 33 keeps column accesses conflict-free.
// ---------------------------------------------------------------------------
__global__ void solve_kernel(const float* __restrict__ omega_child,
                             const float* __restrict__ mu_s)
{
    __shared__ float A[KK * 33];
    const int i = blockIdx.x;
    const int t = threadIdx.x;       // 0..127
    const int lane = t & 31, w = t >> 5;

    // Load + reduce omega_child[i] over G (1024 floats = 256 float4)
    const float4* oc4 = (const float4*)(omega_child + (size_t)i * GG * KK * KK);
    #pragma unroll
    for (int q = t; q < 256; q += 128) {
        float4 s = make_float4(0.f, 0.f, 0.f, 0.f);
        #pragma unroll
        for (int g = 0; g < GG; g++) {
            float4 v = oc4[g * 256 + q];
            s.x += v.x; s.y += v.y; s.z += v.z; s.w += v.w;
        }
        const int e = q * 4;
        const int r = e >> 5, c = e & 31;
        A[r * 33 + c + 0] = s.x;
        A[r * 33 + c + 1] = s.y;
        A[r * 33 + c + 2] = s.z;
        A[r * 33 + c + 3] = s.w;
    }
    if (t < KK) {
        const float* mu = mu_s + (size_t)i * GG * KK;
        float s = 0.f;
        #pragma unroll
        for (int g = 0; g < GG; g++) s += mu[g * KK + t];
        A[t * 33 + 32] = s;
    }
    __syncthreads();

    // Forward elimination (SPD: no pivoting). Column k is read but never
    // written (left stale) -> no intra-warp RAW hazard on A[r][k].
    for (int k = 0; k < KK - 1; k++) {
        const float invp = 1.0f / A[k * 33 + k];
        const int c = k + 1 + lane;
        for (int r = k + 1 + w; r < KK; r += 4) {
            const float m = A[r * 33 + k] * invp;
            if (c <= 32) A[r * 33 + c] -= m * A[k * 33 + c];
        }
        __syncthreads();
    }

    // Backward Jordan on the b column only.
    for (int k = KK - 1; k >= 1; k--) {
        if (t < k) {
            const float xk = A[k * 33 + 32] / A[k * 33 + k];
            A[t * 33 + 32] -= A[t * 33 + k] * xk;
        }
        __syncthreads();
    }
    if (t < KK)
        g_V[(size_t)i * KK + t] = A[t * 33 + 32] / A[t * 33 + t];
}

// ---------------------------------------------------------------------------
// Kernel 2: per (cluster a, i-split s): accumulate
//   Z  = sum_i w_ia,  cnt = sum_i mask,  S1[l] = sum_i w v_l,
//   S2[l,m] = sum_i w v_l v_m
// Fuses the W spatial mean + mask (reads raw W). 256 threads; thread t owns
// pairs (l = t>>3, m = (t&7)*4 .. +3).
// ---------------------------------------------------------------------------
__global__ void accum_kernel(const float* __restrict__ W)
{
    const int a = blockIdx.x;
    const int s = blockIdx.y;
    const int t = threadIdx.x;     // 0..255
    const int i0base = s * CHUNK;

    __shared__ float sv[32 * 32];    // v tile [ii][l]
    __shared__ float swv[32 * 33];   // (w*v) tile, padded stride 33
    __shared__ float sw[32];         // masked weights
    __shared__ float red[16];

    const int l  = t >> 3;
    const int mg = t & 7;

    float acc0 = 0.f, acc1 = 0.f, acc2 = 0.f, acc3 = 0.f;
    float accS1 = 0.f, accZ = 0.f, accCnt = 0.f;

    for (int tile = 0; tile < CHUNK / 32; tile++) {
        const int ib = i0base + tile * 32;
        // load V tile: thread -> (ii = t>>3, c = t&7), one float4 each
        {
            const int ii = t >> 3, c = t & 7;
            const float4* vp = (const float4*)(g_V + (size_t)(ib + ii) * KK);
            ((float4*)sv)[ii * 8 + c] = vp[c];
        }
        // load + reduce W over G: threads t<128, 4 threads per i
        if (t < 128) {
            const int ii = t >> 2, part = t & 3;
            const float4* wp =
                (const float4*)(W + ((size_t)(ib + ii) * MM + a) * GG);
            const float4 w4 = wp[part];
            float ssum = w4.x + w4.y + w4.z + w4.w;
            ssum += __shfl_xor_sync(0xffffffffu, ssum, 1);
            ssum += __shfl_xor_sync(0xffffffffu, ssum, 2);
            if (part == 0) {
                const float wm = ssum * 0.0625f;            // /16 mean
                const int ok = (wm >= 1e-6f);
                const float wmm = ok ? wm : 0.0f;
                sw[ii] = wmm;
                accZ += wmm;
                accCnt += ok ? 1.0f : 0.0f;
            }
        }
        __syncthreads();
        // wv = w * v
        #pragma unroll
        for (int e = t; e < 1024; e += 256) {
            const int ii = e >> 5, ll = e & 31;
            swv[ii * 33 + ll] = sw[ii] * sv[ii * 32 + ll];
        }
        __syncthreads();
        // S1 partial: this thread's 4 designated ii's for its l
        {
            const int iib = mg * 4;
            accS1 += swv[(iib + 0) * 33 + l] + swv[(iib + 1) * 33 + l]
                   + swv[(iib + 2) * 33 + l] + swv[(iib + 3) * 33 + l];
        }
        // main rank-1 accumulation over the tile
        const float4* sv4 = (const float4*)sv;
        #pragma unroll
        for (int ii = 0; ii < 32; ii++) {
            const float wvl = swv[ii * 33 + l];
            const float4 vm = sv4[ii * 8 + mg];
            acc0 += wvl * vm.x;
            acc1 += wvl * vm.y;
            acc2 += wvl * vm.z;
            acc3 += wvl * vm.w;
        }
        __syncthreads();
    }

    // S2 partial: thread owns its 4 unique (l,m) slots
    float* p2 = g_partS2 + ((size_t)a * NS + s) * (KK * KK) + l * KK + mg * 4;
    p2[0] = acc0; p2[1] = acc1; p2[2] = acc2; p2[3] = acc3;

    // S1: reduce over the 8 threads sharing l (aligned lane groups of 8)
    accS1 += __shfl_xor_sync(0xffffffffu, accS1, 1);
    accS1 += __shfl_xor_sync(0xffffffffu, accS1, 2);
    accS1 += __shfl_xor_sync(0xffffffffu, accS1, 4);
    if (mg == 0) g_partS1[((size_t)a * NS + s) * KK + l] = accS1;

    // Z / cnt: block reduce
    float z = accZ, cn = accCnt;
    #pragma unroll
    for (int off = 16; off; off >>= 1) {
        z  += __shfl_xor_sync(0xffffffffu, z, off);
        cn += __shfl_xor_sync(0xffffffffu, cn, off);
    }
    if ((t & 31) == 0) { red[t >> 5] = z; red[8 + (t >> 5)] = cn; }
    __syncthreads();
    if (t == 0) {
        float Z = 0.f, C = 0.f;
        #pragma unroll
        for (int ww = 0; ww < 8; ww++) { Z += red[ww]; C += red[8 + ww]; }
        g_partZ[a * NS + s]   = Z;
        g_partCnt[a * NS + s] = C;
    }
}

// ---------------------------------------------------------------------------
// Kernel 3: per cluster a: psi_a = sum_lm S[l,m] * C[l,m]
//   S = op_avg^T op_avg,  C = S2/Zs - vbar vbar^T,  vbar = S1/Zs
// psi_a = 0 if count < 2.
// ---------------------------------------------------------------------------
__global__ void finalize_kernel(const float* __restrict__ omega_parent,
                                float* __restrict__ out)
{
    const int a = blockIdx.x;
    const int t = threadIdx.x;    // 0..255
    __shared__ float op[32 * 33];
    __shared__ float vbar[32];
    __shared__ float zc[2];
    __shared__ float red[8];

    // op_avg = mean over G (1024 floats = 256 float4; one per thread)
    {
        const float4* opp =
            (const float4*)(omega_parent + (size_t)a * GG * KK * KK);
        float4 sacc = make_float4(0.f, 0.f, 0.f, 0.f);
        #pragma unroll
        for (int g = 0; g < GG; g++) {
            const float4 v = opp[g * 256 + t];
            sacc.x += v.x; sacc.y += v.y; sacc.z += v.z; sacc.w += v.w;
        }
        const int e = t * 4;
        const int r = e >> 5, c = e & 31;
        const float inv = 1.0f / 16.0f;
        op[r * 33 + c + 0] = sacc.x * inv;
        op[r * 33 + c + 1] = sacc.y * inv;
        op[r * 33 + c + 2] = sacc.z * inv;
        op[r * 33 + c + 3] = sacc.w * inv;
    }
    if (t == 0) {
        float Z = 0.f, C = 0.f;
        #pragma unroll
        for (int ss = 0; ss < NS; ss++) {
            Z += g_partZ[a * NS + ss];
            C += g_partCnt[a * NS + ss];
        }
        zc[0] = (Z > 0.f) ? Z : 1.0f;
        zc[1] = C;
    }
    if (t < KK) {
        float s1 = 0.f;
        #pragma unroll
        for (int ss = 0; ss < NS; ss++)
            s1 += g_partS1[(a * NS + ss) * KK + t];
        vbar[t] = s1;            // temp: raw S1; scaled after sync
    }
    __syncthreads();
    const float Zs = zc[0];
    if (t < KK) vbar[t] = vbar[t] / Zs;
    __syncthreads();

    float psi = 0.f;
    #pragma unroll
    for (int j = 0; j < 4; j++) {
        const int e = t + 256 * j;
        const int l = e >> 5, m = e & 31;
        float s2 = 0.f;
        #pragma unroll
        for (int ss = 0; ss < NS; ss++)
            s2 += g_partS2[((size_t)a * NS + ss) * (KK * KK) + e];
        const float C = s2 / Zs - vbar[l] * vbar[m];
        float S = 0.f;
        #pragma unroll
        for (int k = 0; k < KK; k++)
            S += op[k * 33 + l] * op[k * 33 + m];
        psi += S * C;
    }

    #pragma unroll
    for (int off = 16; off; off >>= 1)
        psi += __shfl_xor_sync(0xffffffffu, psi, off);
    if ((t & 31) == 0) red[t >> 5] = psi;
    __syncthreads();
    if (t == 0) {
        float tot = 0.f;
        #pragma unroll
        for (int ww = 0; ww < 8; ww++) tot += red[ww];
        out[a] = (zc[1] >= 2.0f) ? tot : 0.0f;
    }
}

// ---------------------------------------------------------------------------
extern "C" void kernel_launch(void* const* d_in, const int* in_sizes, int n_in,
                              void* d_out, int out_size)
{
    const float* W  = (const float*)d_in[0];   // (N, M, G)
    const float* mu = (const float*)d_in[1];   // (N, G, K)
    const float* oc = (const float*)d_in[2];   // (N, G, K, K)
    const float* op = (const float*)d_in[3];   // (M, G, K, K)
    float* out = (float*)d_out;                // (M,)

    solve_kernel<<<NN, 128>>>(oc, mu);
    accum_kernel<<<dim3(MM, NS), 256>>>(W);
    finalize_kernel<<<MM, 256>>>(op, out);
}